// round 6
// baseline (speedup 1.0000x reference)
#include <cuda_runtime.h>

#define BATCH 2
#define SEQ 2048
#define HEADS 16
#define DK 64
#define DMODEL 1024
#define NTOK (BATCH*SEQ)   // 4096

// Scratch (allocation-free rule: device globals)
__device__ float g_Q[BATCH*HEADS*SEQ*DK];   // [b,h,s,d]
__device__ float g_K[BATCH*HEADS*SEQ*DK];
__device__ float g_V[BATCH*HEADS*SEQ*DK];
__device__ float g_AT[NTOK*DMODEL];         // attention out, [b,s,h*DK]

struct EpiQKV {
  __device__ __forceinline__ void write(int m, int n, float v) const {
    int part = n >> 10;          // 0=q,1=k,2=v
    int w = n & 1023;
    int h = w >> 6, d = w & 63;
    int b = m >> 11, s = m & 2047;
    float* dst = (part == 0) ? g_Q : (part == 1) ? g_K : g_V;
    dst[(((b*HEADS + h)*SEQ) + s)*DK + d] = v;
  }
};

struct EpiOut {
  float* out;
  __device__ __forceinline__ void write(int m, int n, float v) const {
    out[(size_t)m*DMODEL + n] = v;
  }
};

// C[m,n] = sum_k A[m,k] * W[n,k]   (both operands K-contiguous row-major)
// 128x128 tile, BK=16, 256 threads, 8x8 per thread (cols split tx*4 and tx*4+64)
template<bool FROM_GA, class Epi>
__global__ __launch_bounds__(256)
void sgemm_kernel(const float* __restrict__ Ain, const float* __restrict__ W,
                  int M, int N, int K, Epi epi)
{
  __shared__ float As[16][132];
  __shared__ float Bs[16][132];
  const float* A = FROM_GA ? (const float*)g_AT : Ain;
  int bm = blockIdx.y * 128, bn = blockIdx.x * 128;
  int tid = threadIdx.x;
  int tx = tid & 15, ty = tid >> 4;
  float acc[8][8] = {};
  for (int k0 = 0; k0 < K; k0 += 16) {
    #pragma unroll
    for (int L = tid; L < 512; L += 256) {
      int row = L >> 2, kc = (L & 3) << 2;
      float4 av = *(const float4*)(A + (size_t)(bm+row)*K + k0 + kc);
      As[kc+0][row]=av.x; As[kc+1][row]=av.y; As[kc+2][row]=av.z; As[kc+3][row]=av.w;
      float4 bv = *(const float4*)(W + (size_t)(bn+row)*K + k0 + kc);
      Bs[kc+0][row]=bv.x; Bs[kc+1][row]=bv.y; Bs[kc+2][row]=bv.z; Bs[kc+3][row]=bv.w;
    }
    __syncthreads();
    #pragma unroll
    for (int k = 0; k < 16; ++k) {
      float a[8], b[8];
      *(float4*)(a)   = *(const float4*)&As[k][ty*8];
      *(float4*)(a+4) = *(const float4*)&As[k][ty*8+4];
      *(float4*)(b)   = *(const float4*)&Bs[k][tx*4];
      *(float4*)(b+4) = *(const float4*)&Bs[k][tx*4+64];
      #pragma unroll
      for (int i = 0; i < 8; ++i)
        #pragma unroll
        for (int j = 0; j < 8; ++j)
          acc[i][j] = fmaf(a[i], b[j], acc[i][j]);
    }
    __syncthreads();
  }
  #pragma unroll
  for (int i = 0; i < 8; ++i) {
    int m = bm + ty*8 + i;
    #pragma unroll
    for (int j = 0; j < 8; ++j) {
      int n = bn + ((j < 4) ? (tx*4 + j) : (64 + tx*4 + j - 4));
      epi.write(m, n, acc[i][j]);
    }
  }
}

// RoPE in-place on g_Q and g_K. One thread per (row, pair).
__global__ void rope_kernel(const int* __restrict__ pos) {
  int gid = blockIdx.x * blockDim.x + threadIdx.x;
  int lane = gid & 31;                 // pair index 0..31
  int rr = gid >> 5;                   // row id over both tensors
  if (rr >= 2*BATCH*HEADS*SEQ) return;
  int tensor = rr >> 16;               // B*H*S == 65536
  int rem = rr & 65535;
  int s = rem & (SEQ-1);
  float* ptr = tensor ? g_K : g_Q;
  float p = (float)pos[s];
  float freq = __powf(10000.0f, -(float)lane / 32.0f);  // theta^(-2i/d_k)
  float sn, cs;
  sincosf(p * freq, &sn, &cs);
  size_t base = (size_t)rem * 64 + 2*lane;
  float x1 = ptr[base], x2 = ptr[base+1];
  ptr[base]   = x1*cs - x2*sn;
  ptr[base+1] = x1*sn + x2*cs;
}

// Causal flash attention: one block per (b*h, 128 q-rows); one thread per q-row.
// K/V tiles of 64 rows in smem; q + accumulator in registers.
__global__ __launch_bounds__(128)
void attn_kernel() {
  __shared__ float Ks[64*64];
  __shared__ float Vs[64*64];
  int bh = blockIdx.y;
  int qt = blockIdx.x;
  int tid = threadIdx.x;
  int qi = qt*128 + tid;
  const float* Qp = g_Q + ((size_t)bh*SEQ + qi)*DK;
  float q[64];
  #pragma unroll
  for (int d = 0; d < 64; d += 4) {
    float4 v4 = *(const float4*)(Qp + d);
    q[d]=v4.x; q[d+1]=v4.y; q[d+2]=v4.z; q[d+3]=v4.w;
  }
  float acc[64];
  #pragma unroll
  for (int d = 0; d < 64; ++d) acc[d] = 0.f;
  float mmax = -3.0e38f, l = 0.f;
  const float* Kb = g_K + (size_t)bh*SEQ*DK;
  const float* Vb = g_V + (size_t)bh*SEQ*DK;
  int ntiles = qt*2 + 2;
  for (int t = 0; t < ntiles; ++t) {
    int row = tid >> 1, half = (tid & 1)*32;
    const float* ksrc = Kb + (size_t)(t*64+row)*64 + half;
    const float* vsrc = Vb + (size_t)(t*64+row)*64 + half;
    float* kd = Ks + row*64 + half;
    float* vd = Vs + row*64 + half;
    #pragma unroll
    for (int i = 0; i < 32; i += 4) {
      *(float4*)(kd+i) = *(const float4*)(ksrc+i);
      *(float4*)(vd+i) = *(const float4*)(vsrc+i);
    }
    __syncthreads();
    int kb = t*64;
    if (kb <= qi) {
      int jmax = min(63, qi - kb);
      for (int j = 0; j <= jmax; ++j) {
        const float4* kr = (const float4*)(Ks + j*64);
        float s0=0.f, s1=0.f, s2=0.f, s3=0.f;
        #pragma unroll
        for (int d4 = 0; d4 < 16; ++d4) {
          float4 kv = kr[d4];          // warp-uniform address -> smem broadcast
          s0 = fmaf(q[d4*4+0], kv.x, s0);
          s1 = fmaf(q[d4*4+1], kv.y, s1);
          s2 = fmaf(q[d4*4+2], kv.z, s2);
          s3 = fmaf(q[d4*4+3], kv.w, s3);
        }
        float sc = ((s0+s1)+(s2+s3)) * 0.125f;   // 1/sqrt(64)
        float p;
        if (sc > mmax) {
          float corr = __expf(mmax - sc);
          l *= corr;
          #pragma unroll
          for (int d = 0; d < 64; ++d) acc[d] *= corr;
          mmax = sc;
          p = 1.0f;
        } else {
          p = __expf(sc - mmax);
        }
        l += p;
        const float4* vr = (const float4*)(Vs + j*64);
        #pragma unroll
        for (int d4 = 0; d4 < 16; ++d4) {
          float4 vv = vr[d4];
          acc[d4*4+0] = fmaf(p, vv.x, acc[d4*4+0]);
          acc[d4*4+1] = fmaf(p, vv.y, acc[d4*4+1]);
          acc[d4*4+2] = fmaf(p, vv.z, acc[d4*4+2]);
          acc[d4*4+3] = fmaf(p, vv.w, acc[d4*4+3]);
        }
      }
    }
    __syncthreads();
  }
  float inv = 1.0f / l;
  int b = bh >> 4, h = bh & 15;
  float* op = g_AT + ((size_t)(b*SEQ + qi)*HEADS + h)*DK;
  #pragma unroll
  for (int d = 0; d < 64; d += 4) {
    float4 o4 = make_float4(acc[d]*inv, acc[d+1]*inv, acc[d+2]*inv, acc[d+3]*inv);
    *(float4*)(op + d) = o4;
  }
}

extern "C" void kernel_launch(void* const* d_in, const int* in_sizes, int n_in,
                              void* d_out, int out_size) {
  const float* x    = (const float*)d_in[0];
  const int*   pos  = (const int*)d_in[1];      // token_positions (int32)
  const float* wqkv = (const float*)d_in[2];    // [3072, 1024]
  const float* wo   = (const float*)d_in[3];    // [1024, 1024]
  float* out = (float*)d_out;

  // 1) QKV projection, scatter into head-major Q/K/V
  dim3 g1((3*DMODEL)/128, NTOK/128);
  sgemm_kernel<false, EpiQKV><<<g1, 256>>>(x, wqkv, NTOK, 3*DMODEL, DMODEL, EpiQKV{});

  // 2) RoPE in-place on Q and K
  int total = 2*BATCH*HEADS*SEQ*32;
  rope_kernel<<<total/128, 128>>>(pos);

  // 3) Causal flash attention
  dim3 g2(SEQ/128, BATCH*HEADS);
  attn_kernel<<<g2, 128>>>();

  // 4) Output projection
  dim3 g3(DMODEL/128, NTOK/128);
  sgemm_kernel<true, EpiOut><<<g3, 256>>>(nullptr, wo, NTOK, DMODEL, DMODEL, EpiOut{out});
}

// round 7
// speedup vs baseline: 1.3750x; 1.3750x over previous
#include <cuda_runtime.h>
#include <cstdint>

#define BATCH 2
#define SEQ 2048
#define HEADS 16
#define DK 64
#define DMODEL 1024
#define NTOK (BATCH*SEQ)   // 4096

// Scratch (allocation-free rule: device globals)
__device__ float g_Q[BATCH*HEADS*SEQ*DK];   // [b,h,s,d]
__device__ float g_K[BATCH*HEADS*SEQ*DK];
__device__ float g_V[BATCH*HEADS*SEQ*DK];
__device__ float g_AT[NTOK*DMODEL];         // attention out, [b,s,h*DK]

struct EpiQKV {
  __device__ __forceinline__ void write(int m, int n, float v) const {
    int part = n >> 10;          // 0=q,1=k,2=v
    int w = n & 1023;
    int h = w >> 6, d = w & 63;
    int b = m >> 11, s = m & 2047;
    float* dst = (part == 0) ? g_Q : (part == 1) ? g_K : g_V;
    dst[(((b*HEADS + h)*SEQ) + s)*DK + d] = v;
  }
};

struct EpiOut {
  float* out;
  __device__ __forceinline__ void write(int m, int n, float v) const {
    out[(size_t)m*DMODEL + n] = v;
  }
};

__device__ __forceinline__ uint32_t f2tf32(float f) {
  uint32_t u;
  asm("cvt.rna.tf32.f32 %0, %1;" : "=r"(u) : "f"(f));
  return u;
}

// ============================================================================
// TF32 tensor-core GEMM: C[m,n] = sum_k A[m,k] * W[n,k]
// Block tile 128x128, BK=16, 256 threads = 8 warps (2 m x 4 n),
// each warp computes 64x32 via 4x4 grid of m16n8k8 MMAs.
// Double-buffered cp.async smem, pad-20 rows (conflict-free fragment LDS).
// ============================================================================
#define BK 16
#define PAD 20

template<bool FROM_GA, class Epi>
__global__ __launch_bounds__(256)
void mma_gemm(const float* __restrict__ Ain, const float* __restrict__ W,
              int K, Epi epi)
{
  __shared__ float As[2][128*PAD];
  __shared__ float Bs[2][128*PAD];
  const float* A = FROM_GA ? (const float*)g_AT : Ain;
  const int bm = blockIdx.y * 128, bn = blockIdx.x * 128;
  const int tid = threadIdx.x;
  const int warp = tid >> 5, lane = tid & 31;
  const int wm = warp >> 2, wn = warp & 3;     // warp grid 2 x 4
  const int gq = lane >> 2, tg = lane & 3;     // group-row, thread-in-group

  float acc[4][4][4];
  #pragma unroll
  for (int i = 0; i < 4; ++i)
    #pragma unroll
    for (int j = 0; j < 4; ++j)
      #pragma unroll
      for (int r = 0; r < 4; ++r) acc[i][j][r] = 0.f;

  auto load_stage = [&](int stage, int k0) {
    #pragma unroll
    for (int c = tid; c < 512; c += 256) {
      int row = c >> 2, kc = (c & 3) << 2;
      const float* gA = A + (size_t)(bm + row) * K + k0 + kc;
      uint32_t dA = (uint32_t)__cvta_generic_to_shared(&As[stage][row*PAD + kc]);
      asm volatile("cp.async.cg.shared.global [%0], [%1], 16;\n" :: "r"(dA), "l"(gA));
      const float* gB = W + (size_t)(bn + row) * K + k0 + kc;
      uint32_t dB = (uint32_t)__cvta_generic_to_shared(&Bs[stage][row*PAD + kc]);
      asm volatile("cp.async.cg.shared.global [%0], [%1], 16;\n" :: "r"(dB), "l"(gB));
    }
    asm volatile("cp.async.commit_group;\n");
  };

  const int nk = K / BK;
  load_stage(0, 0);

  for (int kt = 0; kt < nk; ++kt) {
    const int stage = kt & 1;
    if (kt + 1 < nk) {
      load_stage(stage ^ 1, (kt + 1) * BK);
      asm volatile("cp.async.wait_group 1;\n");
    } else {
      asm volatile("cp.async.wait_group 0;\n");
    }
    __syncthreads();

    const float* Ab = &As[stage][0];
    const float* Bb = &Bs[stage][0];
    #pragma unroll
    for (int ks = 0; ks < 2; ++ks) {
      uint32_t af[4][4], bf[4][2];
      #pragma unroll
      for (int mt = 0; mt < 4; ++mt) {
        int r0 = wm*64 + mt*16 + gq;
        int kc = ks*8 + tg;
        af[mt][0] = f2tf32(Ab[(r0    )*PAD + kc    ]);
        af[mt][1] = f2tf32(Ab[(r0 + 8)*PAD + kc    ]);
        af[mt][2] = f2tf32(Ab[(r0    )*PAD + kc + 4]);
        af[mt][3] = f2tf32(Ab[(r0 + 8)*PAD + kc + 4]);
      }
      #pragma unroll
      for (int nt = 0; nt < 4; ++nt) {
        int n0 = wn*32 + nt*8 + gq;
        int kc = ks*8 + tg;
        bf[nt][0] = f2tf32(Bb[n0*PAD + kc    ]);
        bf[nt][1] = f2tf32(Bb[n0*PAD + kc + 4]);
      }
      #pragma unroll
      for (int mt = 0; mt < 4; ++mt)
        #pragma unroll
        for (int nt = 0; nt < 4; ++nt)
          asm volatile(
            "mma.sync.aligned.m16n8k8.row.col.f32.tf32.tf32.f32 "
            "{%0,%1,%2,%3}, {%4,%5,%6,%7}, {%8,%9}, {%0,%1,%2,%3};\n"
            : "+f"(acc[mt][nt][0]), "+f"(acc[mt][nt][1]),
              "+f"(acc[mt][nt][2]), "+f"(acc[mt][nt][3])
            : "r"(af[mt][0]), "r"(af[mt][1]), "r"(af[mt][2]), "r"(af[mt][3]),
              "r"(bf[nt][0]), "r"(bf[nt][1]));
    }
    __syncthreads();
  }

  // Epilogue: c0 (gq, 2*tg), c1 (gq, 2*tg+1), c2 (gq+8, 2*tg), c3 (gq+8, 2*tg+1)
  #pragma unroll
  for (int mt = 0; mt < 4; ++mt) {
    int m0 = bm + wm*64 + mt*16 + gq;
    #pragma unroll
    for (int nt = 0; nt < 4; ++nt) {
      int n0 = bn + wn*32 + nt*8 + tg*2;
      epi.write(m0,     n0,     acc[mt][nt][0]);
      epi.write(m0,     n0 + 1, acc[mt][nt][1]);
      epi.write(m0 + 8, n0,     acc[mt][nt][2]);
      epi.write(m0 + 8, n0 + 1, acc[mt][nt][3]);
    }
  }
}

// ============================================================================
// RoPE in-place on g_Q and g_K. One thread per (row, pair).
// ============================================================================
__global__ void rope_kernel(const int* __restrict__ pos) {
  int gid = blockIdx.x * blockDim.x + threadIdx.x;
  int lane = gid & 31;                 // pair index 0..31
  int rr = gid >> 5;                   // row id over both tensors
  if (rr >= 2*BATCH*HEADS*SEQ) return;
  int tensor = rr >> 16;               // B*H*S == 65536
  int rem = rr & 65535;
  int s = rem & (SEQ-1);
  float* ptr = tensor ? g_K : g_Q;
  float p = (float)pos[s];
  float freq = __powf(10000.0f, -(float)lane / 32.0f);
  float sn, cs;
  sincosf(p * freq, &sn, &cs);
  size_t base = (size_t)rem * 64 + 2*lane;
  float x1 = ptr[base], x2 = ptr[base+1];
  ptr[base]   = x1*cs - x2*sn;
  ptr[base+1] = x1*sn + x2*cs;
}

// ============================================================================
// Causal flash attention: one block per (b*h, 128 q-rows); one thread per q-row.
// ============================================================================
__global__ __launch_bounds__(128)
void attn_kernel() {
  __shared__ float Ks[64*64];
  __shared__ float Vs[64*64];
  int bh = blockIdx.y;
  int qt = blockIdx.x;
  int tid = threadIdx.x;
  int qi = qt*128 + tid;
  const float* Qp = g_Q + ((size_t)bh*SEQ + qi)*DK;
  float q[64];
  #pragma unroll
  for (int d = 0; d < 64; d += 4) {
    float4 v4 = *(const float4*)(Qp + d);
    q[d]=v4.x; q[d+1]=v4.y; q[d+2]=v4.z; q[d+3]=v4.w;
  }
  float acc[64];
  #pragma unroll
  for (int d = 0; d < 64; ++d) acc[d] = 0.f;
  float mmax = -3.0e38f, l = 0.f;
  const float* Kb = g_K + (size_t)bh*SEQ*DK;
  const float* Vb = g_V + (size_t)bh*SEQ*DK;
  int ntiles = qt*2 + 2;
  for (int t = 0; t < ntiles; ++t) {
    int row = tid >> 1, half = (tid & 1)*32;
    const float* ksrc = Kb + (size_t)(t*64+row)*64 + half;
    const float* vsrc = Vb + (size_t)(t*64+row)*64 + half;
    float* kd = Ks + row*64 + half;
    float* vd = Vs + row*64 + half;
    #pragma unroll
    for (int i = 0; i < 32; i += 4) {
      *(float4*)(kd+i) = *(const float4*)(ksrc+i);
      *(float4*)(vd+i) = *(const float4*)(vsrc+i);
    }
    __syncthreads();
    int kb = t*64;
    if (kb <= qi) {
      int jmax = min(63, qi - kb);
      for (int j = 0; j <= jmax; ++j) {
        const float4* kr = (const float4*)(Ks + j*64);
        float s0=0.f, s1=0.f, s2=0.f, s3=0.f;
        #pragma unroll
        for (int d4 = 0; d4 < 16; ++d4) {
          float4 kv = kr[d4];
          s0 = fmaf(q[d4*4+0], kv.x, s0);
          s1 = fmaf(q[d4*4+1], kv.y, s1);
          s2 = fmaf(q[d4*4+2], kv.z, s2);
          s3 = fmaf(q[d4*4+3], kv.w, s3);
        }
        float sc = ((s0+s1)+(s2+s3)) * 0.125f;
        float p;
        if (sc > mmax) {
          float corr = __expf(mmax - sc);
          l *= corr;
          #pragma unroll
          for (int d = 0; d < 64; ++d) acc[d] *= corr;
          mmax = sc;
          p = 1.0f;
        } else {
          p = __expf(sc - mmax);
        }
        l += p;
        const float4* vr = (const float4*)(Vs + j*64);
        #pragma unroll
        for (int d4 = 0; d4 < 16; ++d4) {
          float4 vv = vr[d4];
          acc[d4*4+0] = fmaf(p, vv.x, acc[d4*4+0]);
          acc[d4*4+1] = fmaf(p, vv.y, acc[d4*4+1]);
          acc[d4*4+2] = fmaf(p, vv.z, acc[d4*4+2]);
          acc[d4*4+3] = fmaf(p, vv.w, acc[d4*4+3]);
        }
      }
    }
    __syncthreads();
  }
  float inv = 1.0f / l;
  int b = bh >> 4, h = bh & 15;
  float* op = g_AT + ((size_t)(b*SEQ + qi)*HEADS + h)*DK;
  #pragma unroll
  for (int d = 0; d < 64; d += 4) {
    float4 o4 = make_float4(acc[d]*inv, acc[d+1]*inv, acc[d+2]*inv, acc[d+3]*inv);
    *(float4*)(op + d) = o4;
  }
}

extern "C" void kernel_launch(void* const* d_in, const int* in_sizes, int n_in,
                              void* d_out, int out_size) {
  const float* x    = (const float*)d_in[0];
  const int*   pos  = (const int*)d_in[1];      // token_positions (int32)
  const float* wqkv = (const float*)d_in[2];    // [3072, 1024]
  const float* wo   = (const float*)d_in[3];    // [1024, 1024]
  float* out = (float*)d_out;

  // 1) QKV projection (TF32 MMA), scatter into head-major Q/K/V
  dim3 g1((3*DMODEL)/128, NTOK/128);
  mma_gemm<false, EpiQKV><<<g1, 256>>>(x, wqkv, DMODEL, EpiQKV{});

  // 2) RoPE in-place on Q and K
  int total = 2*BATCH*HEADS*SEQ*32;
  rope_kernel<<<total/128, 128>>>(pos);

  // 3) Causal flash attention
  dim3 g2(SEQ/128, BATCH*HEADS);
  attn_kernel<<<g2, 128>>>();

  // 4) Output projection (TF32 MMA)
  dim3 g3(DMODEL/128, NTOK/128);
  mma_gemm<true, EpiOut><<<g3, 256>>>(nullptr, wo, DMODEL, EpiOut{out});
}

// round 8
// speedup vs baseline: 3.5483x; 2.5805x over previous
#include <cuda_runtime.h>
#include <cstdint>

#define BATCH 2
#define SEQ 2048
#define HEADS 16
#define DK 64
#define DMODEL 1024
#define NTOK (BATCH*SEQ)   // 4096

// Scratch (allocation-free rule: device globals)
__device__ float g_Q[BATCH*HEADS*SEQ*DK];   // [b,h,s,d]
__device__ float g_K[BATCH*HEADS*SEQ*DK];
__device__ float g_V[BATCH*HEADS*SEQ*DK];
__device__ float g_AT[NTOK*DMODEL];         // attention out, [b,s,h*DK]

struct EpiQKV {
  __device__ __forceinline__ void write(int m, int n, float v) const {
    int part = n >> 10;          // 0=q,1=k,2=v
    int w = n & 1023;
    int h = w >> 6, d = w & 63;
    int b = m >> 11, s = m & 2047;
    float* dst = (part == 0) ? g_Q : (part == 1) ? g_K : g_V;
    dst[(((b*HEADS + h)*SEQ) + s)*DK + d] = v;
  }
};

struct EpiOut {
  float* out;
  __device__ __forceinline__ void write(int m, int n, float v) const {
    out[(size_t)m*DMODEL + n] = v;
  }
};

__device__ __forceinline__ uint32_t f2tf32(float f) {
  uint32_t u;
  asm("cvt.rna.tf32.f32 %0, %1;" : "=r"(u) : "f"(f));
  return u;
}

__device__ __forceinline__ float ex2(float x) {
  float y;
  asm("ex2.approx.ftz.f32 %0, %1;" : "=f"(y) : "f"(x));
  return y;
}

__device__ __forceinline__ void mma_tf32(float* c, const uint32_t* a,
                                         uint32_t b0, uint32_t b1) {
  asm volatile(
    "mma.sync.aligned.m16n8k8.row.col.f32.tf32.tf32.f32 "
    "{%0,%1,%2,%3}, {%4,%5,%6,%7}, {%8,%9}, {%0,%1,%2,%3};\n"
    : "+f"(c[0]), "+f"(c[1]), "+f"(c[2]), "+f"(c[3])
    : "r"(a[0]), "r"(a[1]), "r"(a[2]), "r"(a[3]), "r"(b0), "r"(b1));
}

// ============================================================================
// TF32 tensor-core GEMM: C[m,n] = sum_k A[m,k] * W[n,k]  (unchanged, working)
// ============================================================================
#define BK 16
#define PAD 20

template<bool FROM_GA, class Epi>
__global__ __launch_bounds__(256)
void mma_gemm(const float* __restrict__ Ain, const float* __restrict__ W,
              int K, Epi epi)
{
  __shared__ float As[2][128*PAD];
  __shared__ float Bs[2][128*PAD];
  const float* A = FROM_GA ? (const float*)g_AT : Ain;
  const int bm = blockIdx.y * 128, bn = blockIdx.x * 128;
  const int tid = threadIdx.x;
  const int warp = tid >> 5, lane = tid & 31;
  const int wm = warp >> 2, wn = warp & 3;
  const int gq = lane >> 2, tg = lane & 3;

  float acc[4][4][4];
  #pragma unroll
  for (int i = 0; i < 4; ++i)
    #pragma unroll
    for (int j = 0; j < 4; ++j)
      #pragma unroll
      for (int r = 0; r < 4; ++r) acc[i][j][r] = 0.f;

  auto load_stage = [&](int stage, int k0) {
    #pragma unroll
    for (int c = tid; c < 512; c += 256) {
      int row = c >> 2, kc = (c & 3) << 2;
      const float* gA = A + (size_t)(bm + row) * K + k0 + kc;
      uint32_t dA = (uint32_t)__cvta_generic_to_shared(&As[stage][row*PAD + kc]);
      asm volatile("cp.async.cg.shared.global [%0], [%1], 16;\n" :: "r"(dA), "l"(gA));
      const float* gB = W + (size_t)(bn + row) * K + k0 + kc;
      uint32_t dB = (uint32_t)__cvta_generic_to_shared(&Bs[stage][row*PAD + kc]);
      asm volatile("cp.async.cg.shared.global [%0], [%1], 16;\n" :: "r"(dB), "l"(gB));
    }
    asm volatile("cp.async.commit_group;\n");
  };

  const int nk = K / BK;
  load_stage(0, 0);

  for (int kt = 0; kt < nk; ++kt) {
    const int stage = kt & 1;
    if (kt + 1 < nk) {
      load_stage(stage ^ 1, (kt + 1) * BK);
      asm volatile("cp.async.wait_group 1;\n");
    } else {
      asm volatile("cp.async.wait_group 0;\n");
    }
    __syncthreads();

    const float* Ab = &As[stage][0];
    const float* Bb = &Bs[stage][0];
    #pragma unroll
    for (int ks = 0; ks < 2; ++ks) {
      uint32_t af[4][4], bf[4][2];
      #pragma unroll
      for (int mt = 0; mt < 4; ++mt) {
        int r0 = wm*64 + mt*16 + gq;
        int kc = ks*8 + tg;
        af[mt][0] = f2tf32(Ab[(r0    )*PAD + kc    ]);
        af[mt][1] = f2tf32(Ab[(r0 + 8)*PAD + kc    ]);
        af[mt][2] = f2tf32(Ab[(r0    )*PAD + kc + 4]);
        af[mt][3] = f2tf32(Ab[(r0 + 8)*PAD + kc + 4]);
      }
      #pragma unroll
      for (int nt = 0; nt < 4; ++nt) {
        int n0 = wn*32 + nt*8 + gq;
        int kc = ks*8 + tg;
        bf[nt][0] = f2tf32(Bb[n0*PAD + kc    ]);
        bf[nt][1] = f2tf32(Bb[n0*PAD + kc + 4]);
      }
      #pragma unroll
      for (int mt = 0; mt < 4; ++mt)
        #pragma unroll
        for (int nt = 0; nt < 4; ++nt)
          mma_tf32(acc[mt][nt], af[mt], bf[nt][0], bf[nt][1]);
    }
    __syncthreads();
  }

  #pragma unroll
  for (int mt = 0; mt < 4; ++mt) {
    int m0 = bm + wm*64 + mt*16 + gq;
    #pragma unroll
    for (int nt = 0; nt < 4; ++nt) {
      int n0 = bn + wn*32 + nt*8 + tg*2;
      epi.write(m0,     n0,     acc[mt][nt][0]);
      epi.write(m0,     n0 + 1, acc[mt][nt][1]);
      epi.write(m0 + 8, n0,     acc[mt][nt][2]);
      epi.write(m0 + 8, n0 + 1, acc[mt][nt][3]);
    }
  }
}

// ============================================================================
// RoPE in-place on g_Q and g_K.
// ============================================================================
__global__ void rope_kernel(const int* __restrict__ pos) {
  int gid = blockIdx.x * blockDim.x + threadIdx.x;
  int lane = gid & 31;
  int rr = gid >> 5;
  if (rr >= 2*BATCH*HEADS*SEQ) return;
  int tensor = rr >> 16;
  int rem = rr & 65535;
  int s = rem & (SEQ-1);
  float* ptr = tensor ? g_K : g_Q;
  float p = (float)pos[s];
  float freq = __powf(10000.0f, -(float)lane / 32.0f);
  float sn, cs;
  sincosf(p * freq, &sn, &cs);
  size_t base = (size_t)rem * 64 + 2*lane;
  float x1 = ptr[base], x2 = ptr[base+1];
  ptr[base]   = x1*cs - x2*sn;
  ptr[base+1] = x1*sn + x2*cs;
}

// ============================================================================
// TF32-MMA causal flash attention.
// Block = (qt, bh): 128 q-rows, 256 threads, 8 warps x 16 rows each.
// K/V tiles of 64 keys, double-buffered dynamic smem (cp.async).
// ============================================================================
#define KP 68              // K tile row pitch (floats): banks (4*gq+tg) distinct
#define VP 72              // V tile row pitch: banks (8*tg'+gq) distinct
#define STAGE_F (64*KP + 64*VP)
#define CSCALE 0.18033688011112042f   // (1/8) * log2(e)

__global__ __launch_bounds__(256)
void attn_mma_kernel() {
  extern __shared__ float smem[];
  const int bh = blockIdx.y;
  const int qt = blockIdx.x;
  const int qbase = qt * 128;
  const int tid = threadIdx.x;
  const int warp = tid >> 5, lane = tid & 31;
  const int gq = lane >> 2, tg = lane & 3;
  const int wq = warp * 16;                 // warp's row offset in the q-tile

  const float* Kb = g_K + (size_t)bh*SEQ*DK;
  const float* Vb = g_V + (size_t)bh*SEQ*DK;

  // Q fragments: rows (qbase+wq+gq, +8), cols ks*8 + tg, tg+4
  uint32_t qaf[8][4];
  {
    const float* Q0 = g_Q + ((size_t)bh*SEQ + qbase + wq + gq) * DK;
    const float* Q1 = Q0 + 8*DK;
    #pragma unroll
    for (int ks = 0; ks < 8; ++ks) {
      int c = ks*8 + tg;
      qaf[ks][0] = f2tf32(Q0[c]);
      qaf[ks][1] = f2tf32(Q1[c]);
      qaf[ks][2] = f2tf32(Q0[c+4]);
      qaf[ks][3] = f2tf32(Q1[c+4]);
    }
  }

  float oacc[8][4];
  #pragma unroll
  for (int nd = 0; nd < 8; ++nd)
    #pragma unroll
    for (int r = 0; r < 4; ++r) oacc[nd][r] = 0.f;
  float m0 = -1e30f, m1 = -1e30f, l0 = 0.f, l1 = 0.f;

  auto load_tile = [&](int stage, int t) {
    float* Ks = smem + stage*STAGE_F;
    float* Vs = Ks + 64*KP;
    const float* Kg = Kb + (size_t)t*64*DK;
    const float* Vg = Vb + (size_t)t*64*DK;
    #pragma unroll
    for (int i = 0; i < 4; ++i) {
      int idx = i*256 + tid;
      int row = idx >> 4, c4 = (idx & 15) << 2;
      uint32_t dK = (uint32_t)__cvta_generic_to_shared(&Ks[row*KP + c4]);
      asm volatile("cp.async.cg.shared.global [%0], [%1], 16;\n"
                   :: "r"(dK), "l"(Kg + row*DK + c4));
      uint32_t dV = (uint32_t)__cvta_generic_to_shared(&Vs[row*VP + c4]);
      asm volatile("cp.async.cg.shared.global [%0], [%1], 16;\n"
                   :: "r"(dV), "l"(Vg + row*DK + c4));
    }
    asm volatile("cp.async.commit_group;\n");
  };

  const int ntiles = qt*2 + 2;
  load_tile(0, 0);

  for (int t = 0; t < ntiles; ++t) {
    if (t + 1 < ntiles) {
      load_tile((t+1) & 1, t+1);
      asm volatile("cp.async.wait_group 1;\n");
    } else {
      asm volatile("cp.async.wait_group 0;\n");
    }
    __syncthreads();

    const float* Ks = smem + (t & 1)*STAGE_F;
    const float* Vs = Ks + 64*KP;

    // Skip tiles fully above the causal diagonal for this warp's rows
    if (t*64 <= qbase + wq + 15) {
      // ---- S = Q @ K^T (raw dot) ----
      float sacc[8][4];
      #pragma unroll
      for (int nt = 0; nt < 8; ++nt) {
        #pragma unroll
        for (int r = 0; r < 4; ++r) sacc[nt][r] = 0.f;
        const float* Krow = Ks + (nt*8 + gq)*KP;
        #pragma unroll
        for (int ks = 0; ks < 8; ++ks) {
          uint32_t b0 = f2tf32(Krow[ks*8 + tg]);
          uint32_t b1 = f2tf32(Krow[ks*8 + tg + 4]);
          mma_tf32(sacc[nt], qaf[ks], b0, b1);
        }
      }

      // ---- scale (log2 space) + causal mask ----
      const int r0g = qbase + wq + gq;       // global row of c0/c1
      const int r1g = r0g + 8;               // global row of c2/c3
      const bool needm = (t*64 + 63 > qbase + wq);
      #pragma unroll
      for (int nt = 0; nt < 8; ++nt) {
        int c0 = t*64 + nt*8 + 2*tg, c1 = c0 + 1;
        float v0 = sacc[nt][0]*CSCALE, v1 = sacc[nt][1]*CSCALE;
        float v2 = sacc[nt][2]*CSCALE, v3 = sacc[nt][3]*CSCALE;
        if (needm) {
          if (c0 > r0g) v0 = -1e30f;
          if (c1 > r0g) v1 = -1e30f;
          if (c0 > r1g) v2 = -1e30f;
          if (c1 > r1g) v3 = -1e30f;
        }
        sacc[nt][0]=v0; sacc[nt][1]=v1; sacc[nt][2]=v2; sacc[nt][3]=v3;
      }

      // ---- online softmax ----
      float mx0 = -1e30f, mx1 = -1e30f;
      #pragma unroll
      for (int nt = 0; nt < 8; ++nt) {
        mx0 = fmaxf(mx0, fmaxf(sacc[nt][0], sacc[nt][1]));
        mx1 = fmaxf(mx1, fmaxf(sacc[nt][2], sacc[nt][3]));
      }
      mx0 = fmaxf(mx0, __shfl_xor_sync(0xffffffffu, mx0, 1));
      mx0 = fmaxf(mx0, __shfl_xor_sync(0xffffffffu, mx0, 2));
      mx1 = fmaxf(mx1, __shfl_xor_sync(0xffffffffu, mx1, 1));
      mx1 = fmaxf(mx1, __shfl_xor_sync(0xffffffffu, mx1, 2));
      float mn0 = fmaxf(m0, mx0), mn1 = fmaxf(m1, mx1);
      float corr0 = ex2(m0 - mn0), corr1 = ex2(m1 - mn1);
      m0 = mn0; m1 = mn1;

      float rs0 = 0.f, rs1 = 0.f;
      #pragma unroll
      for (int nt = 0; nt < 8; ++nt) {
        float p0 = ex2(sacc[nt][0] - m0); sacc[nt][0] = p0; rs0 += p0;
        float p1 = ex2(sacc[nt][1] - m0); sacc[nt][1] = p1; rs0 += p1;
        float p2 = ex2(sacc[nt][2] - m1); sacc[nt][2] = p2; rs1 += p2;
        float p3 = ex2(sacc[nt][3] - m1); sacc[nt][3] = p3; rs1 += p3;
      }
      rs0 += __shfl_xor_sync(0xffffffffu, rs0, 1);
      rs0 += __shfl_xor_sync(0xffffffffu, rs0, 2);
      rs1 += __shfl_xor_sync(0xffffffffu, rs1, 1);
      rs1 += __shfl_xor_sync(0xffffffffu, rs1, 2);
      l0 = l0*corr0 + rs0;
      l1 = l1*corr1 + rs1;

      #pragma unroll
      for (int nd = 0; nd < 8; ++nd) {
        oacc[nd][0] *= corr0; oacc[nd][1] *= corr0;
        oacc[nd][2] *= corr1; oacc[nd][3] *= corr1;
      }

      // ---- O += P @ V ----
      const int lane_lo = (lane & 28) | (tg >> 1);
      const int lane_hi = lane_lo + 2;
      #pragma unroll
      for (int kk = 0; kk < 8; ++kk) {
        // C-layout (cols 2tg,2tg+1) -> A-layout (cols tg, tg+4) via shfl
        float x0 = __shfl_sync(0xffffffffu, sacc[kk][0], lane_lo);
        float x1 = __shfl_sync(0xffffffffu, sacc[kk][1], lane_lo);
        float x2 = __shfl_sync(0xffffffffu, sacc[kk][2], lane_lo);
        float x3 = __shfl_sync(0xffffffffu, sacc[kk][3], lane_lo);
        float y0 = __shfl_sync(0xffffffffu, sacc[kk][0], lane_hi);
        float y1 = __shfl_sync(0xffffffffu, sacc[kk][1], lane_hi);
        float y2 = __shfl_sync(0xffffffffu, sacc[kk][2], lane_hi);
        float y3 = __shfl_sync(0xffffffffu, sacc[kk][3], lane_hi);
        bool odd = (tg & 1);
        uint32_t paf[4];
        paf[0] = f2tf32(odd ? x1 : x0);   // (row gq,   k=tg)
        paf[1] = f2tf32(odd ? x3 : x2);   // (row gq+8, k=tg)
        paf[2] = f2tf32(odd ? y1 : y0);   // (row gq,   k=tg+4)
        paf[3] = f2tf32(odd ? y3 : y2);   // (row gq+8, k=tg+4)
        const float* Vr0 = Vs + (kk*8 + tg)*VP + gq;
        const float* Vr1 = Vs + (kk*8 + tg + 4)*VP + gq;
        #pragma unroll
        for (int nd = 0; nd < 8; ++nd) {
          uint32_t b0 = f2tf32(Vr0[nd*8]);
          uint32_t b1 = f2tf32(Vr1[nd*8]);
          mma_tf32(oacc[nd], paf, b0, b1);
        }
      }
    }
    __syncthreads();
  }

  // ---- epilogue: write [b,s,h*64] ----
  const int b = bh >> 4, h = bh & 15;
  const float inv0 = 1.0f / l0, inv1 = 1.0f / l1;
  const int q0 = qbase + wq + gq;
  float* o0 = g_AT + ((size_t)(b*SEQ + q0))*DMODEL + h*DK;
  float* o1 = o0 + (size_t)8*DMODEL;
  #pragma unroll
  for (int nd = 0; nd < 8; ++nd) {
    int c = nd*8 + 2*tg;
    float2 w0 = make_float2(oacc[nd][0]*inv0, oacc[nd][1]*inv0);
    float2 w1 = make_float2(oacc[nd][2]*inv1, oacc[nd][3]*inv1);
    *(float2*)(o0 + c) = w0;
    *(float2*)(o1 + c) = w1;
  }
}

extern "C" void kernel_launch(void* const* d_in, const int* in_sizes, int n_in,
                              void* d_out, int out_size) {
  const float* x    = (const float*)d_in[0];
  const int*   pos  = (const int*)d_in[1];      // token_positions (int32)
  const float* wqkv = (const float*)d_in[2];    // [3072, 1024]
  const float* wo   = (const float*)d_in[3];    // [1024, 1024]
  float* out = (float*)d_out;

  // 1) QKV projection (TF32 MMA), scatter into head-major Q/K/V
  dim3 g1((3*DMODEL)/128, NTOK/128);
  mma_gemm<false, EpiQKV><<<g1, 256>>>(x, wqkv, DMODEL, EpiQKV{});

  // 2) RoPE in-place on Q and K
  int total = 2*BATCH*HEADS*SEQ*32;
  rope_kernel<<<total/128, 128>>>(pos);

  // 3) Causal flash attention (TF32 MMA), dynamic smem double buffer
  const int smem_bytes = 2 * STAGE_F * (int)sizeof(float);   // 71680
  cudaFuncSetAttribute(attn_mma_kernel,
                       cudaFuncAttributeMaxDynamicSharedMemorySize, smem_bytes);
  dim3 g2(SEQ/128, BATCH*HEADS);
  attn_mma_kernel<<<g2, 256, smem_bytes>>>();

  // 4) Output projection (TF32 MMA)
  dim3 g3(DMODEL/128, NTOK/128);
  mma_gemm<true, EpiOut><<<g3, 256>>>(nullptr, wo, DMODEL, EpiOut{out});
}